// round 3
// baseline (speedup 1.0000x reference)
#include <cuda_runtime.h>

// CostVolume3D: B=8, H=128, W=256, C=8, MAX_DISP=12 -> D=23.
// The reference's tile(..., D) + raw row-major reshape means every tiled
// tensor read collapses to orig.flat[p / 23] in the new flat index space.
// Output flat q ranges over (x=0..B*D-1, h2, w2); H*W = 32768 = 2^15.

#define B_ 8
#define H_ 128
#define W_ 256
#define C_ 8
#define D_ 23

static constexpr int TOTAL = B_ * H_ * W_ * D_;   // 6,029,312 outputs
static constexpr int NF    = B_ * H_ * W_ * C_;   // 2,097,152 feat elements

__global__ void __launch_bounds__(256)
costvol3d_kernel(const float* __restrict__ fl,
                 const float* __restrict__ fr,
                 const float* __restrict__ wf,
                 float* __restrict__ out)
{
    int q = blockIdx.x * blockDim.x + threadIdx.x;
    if (q >= TOTAL) return;

    const unsigned uq = (unsigned)q;
    const int w2   = q & (W_ - 1);     // w coordinate
    const int base = q - w2;           // W*(h2 + H*x)
    const int x    = q >> 15;          // q / (H*W)
    const int s    = x % D_;           // shift index (x < 184, cheap const-mod)

    // disp = wflow.flat[q/23] - (s - 11)
    const float disp = __ldg(&wf[uq / 23u]) - (float)(s - (D_ / 2));
    const float xq   = (float)w2 - disp;
    const float x0f  = floorf(xq);
    const float frac = xq - x0f;                 // bilinear weight (pre-clip, as in ref)
    int x0i = (int)x0f;
    x0i = min(max(x0i, 0), W_ - 1);
    const int x1i = min(x0i + 1, W_ - 1);

    // Flat numerators for the three value streams; for c=0..7 the quotient
    // (p+c)/23 takes at most 2 distinct values -> only 2 loads per stream.
    const unsigned pL = uq * 8u;
    const unsigned iL = pL / 23u;  const unsigned rL = pL - iL * 23u;
    const unsigned p0 = (unsigned)(base + x0i) * 8u;
    const unsigned i0 = p0 / 23u;  const unsigned r0 = p0 - i0 * 23u;
    const unsigned p1 = (unsigned)(base + x1i) * 8u;
    const unsigned i1 = p1 / 23u;  const unsigned r1 = p1 - i1 * 23u;

    // The "+1" index is only consumed when the c-loop actually crosses a
    // multiple of 23, in which case it is guaranteed in-bounds; clamp makes
    // the speculative load safe otherwise.
    const unsigned last = (unsigned)(NF - 1);
    const float A0 = __ldg(&fl[iL]);
    const float A1 = __ldg(&fl[min(iL + 1u, last)]);
    const float B0 = __ldg(&fr[i0]);
    const float B1 = __ldg(&fr[min(i0 + 1u, last)]);
    const float C0 = __ldg(&fr[i1]);
    const float C1 = __ldg(&fr[min(i1 + 1u, last)]);

    float acc = 0.0f;
#pragma unroll
    for (unsigned c = 0; c < 8u; c++) {
        const float L  = (rL + c < 23u) ? A0 : A1;
        const float v0 = (r0 + c < 23u) ? B0 : B1;
        const float v1 = (r1 + c < 23u) ? C0 : C1;
        const float wv = fmaf(frac, v1 - v0, v0);  // v0*(1-f) + v1*f
        acc += fabsf(L - wv);
    }
    out[q] = acc;
}

extern "C" void kernel_launch(void* const* d_in, const int* in_sizes, int n_in,
                              void* d_out, int out_size)
{
    const float* feat_l = (const float*)d_in[0];
    const float* feat_r = (const float*)d_in[1];
    const float* wflow  = (const float*)d_in[2];
    float* out = (float*)d_out;

    const int threads = 256;
    const int blocks  = (TOTAL + threads - 1) / threads;  // 23552
    costvol3d_kernel<<<blocks, threads>>>(feat_l, feat_r, wflow, out);
}

// round 5
// speedup vs baseline: 1.4576x; 1.4576x over previous
#include <cuda_runtime.h>

// CostVolume3D: B=8, H=128, W=256, C=8, MAX_DISP=12 -> D=23.
// tile(...,D) + raw reshape => every tiled read is orig.flat[p/23].
// Per output, each of the 3 value streams (L, warp-tap0, warp-tap1) takes at
// most 2 distinct values across c=0..7 (one quotient crossing). Instead of
// 24 compare+selects, split c into <=4 segments with constant values and
// accumulate count * |L - lerp|  (segment-sum). Each thread does 2 outputs.

#define B_ 8
#define H_ 128
#define W_ 256
#define C_ 8
#define D_ 23

static constexpr int TOTAL = B_ * H_ * W_ * D_;   // 6,029,312 (even)
static constexpr int NF    = B_ * H_ * W_ * C_;   // 2,097,152
static constexpr int NW    = B_ * H_ * W_;        // 262,144 wflow elems

__device__ __forceinline__ float cost_one(
    const float* __restrict__ fr,
    float A0, float A1, int rL,
    int w2, int base, float disp)
{
    // Bilinear sample coords (weights computed pre-clip, as in reference)
    const float xq   = (float)w2 - disp;
    const float x0f  = floorf(xq);
    const float frac = xq - x0f;
    int x0i = (int)x0f;
    x0i = min(max(x0i, 0), W_ - 1);
    const int x1i = min(x0i + 1, W_ - 1);

    const unsigned p0 = (unsigned)(base + x0i) * 8u;
    const unsigned i0 = p0 / 23u;
    const int      r0 = (int)(p0 - i0 * 23u);
    const unsigned p1 = (unsigned)(base + x1i) * 8u;
    const unsigned i1 = p1 / 23u;
    const int      r1 = (int)(p1 - i1 * 23u);

    const unsigned last = (unsigned)(NF - 1);
    const float B0 = __ldg(&fr[i0]);
    const float B1 = __ldg(&fr[min(i0 + 1u, last)]);  // clamped speculative;
    const float C0 = __ldg(&fr[i1]);                  // consumed only when the
    const float C1 = __ldg(&fr[min(i1 + 1u, last)]);  // crossing is in-bounds

    // Flip points: stream uses its first value for c < t, t in [1,8]
    const int tL = min(23 - rL, 8);
    const int t0 = min(23 - r0, 8);
    const int t1 = min(23 - r1, 8);
    const int a  = min(tL, min(t0, t1));
    const int c3 = max(tL, max(t0, t1));
    const int b  = tL + t0 + t1 - a - c3;

    // Segment values (ties give zero-length segments -> value irrelevant)
    const float L1  = (tL <= a) ? A1 : A0;
    const float v01 = (t0 <= a) ? B1 : B0;
    const float v11 = (t1 <= a) ? C1 : C0;
    const float L2  = (tL <= b) ? A1 : A0;
    const float v02 = (t0 <= b) ? B1 : B0;
    const float v12 = (t1 <= b) ? C1 : C0;

    const float g0 = fabsf(A0 - fmaf(frac, C0  - B0,  B0 ));
    const float g1 = fabsf(L1 - fmaf(frac, v11 - v01, v01));
    const float g2 = fabsf(L2 - fmaf(frac, v12 - v02, v02));
    const float g3 = fabsf(A1 - fmaf(frac, C1  - B1,  B1 ));

    float acc = __int2float_rn(a) * g0;
    acc = fmaf(__int2float_rn(b - a),  g1, acc);
    acc = fmaf(__int2float_rn(c3 - b), g2, acc);
    acc = fmaf(__int2float_rn(8 - c3), g3, acc);
    return acc;
}

__global__ void __launch_bounds__(256)
costvol3d_kernel(const float* __restrict__ fl,
                 const float* __restrict__ fr,
                 const float* __restrict__ wf,
                 float* __restrict__ out)
{
    const int t  = blockIdx.x * blockDim.x + threadIdx.x;
    const int q0 = t * 2;
    if (q0 >= TOTAL) return;

    // Pair [q0, q0+1] always shares row/batch-slab: boundaries are multiples
    // of 256 and 32768, q0 is even, so w2 < 255 and same x.
    const int w2   = q0 & (W_ - 1);
    const int base = q0 - w2;
    const int x    = q0 >> 15;
    const int s    = x - 23 * ((x * 179) >> 12);   // x % 23, valid for x<184
    const float shiftf = (float)(s - 11);

    // wflow values for the pair: quotient bumps only when rq == 22
    const unsigned wq = (unsigned)q0 / 23u;
    const unsigned rq = (unsigned)q0 - wq * 23u;
    const float wA = __ldg(&wf[wq]);
    const float wB = __ldg(&wf[min(wq + 1u, (unsigned)(NW - 1))]);
    const float disp0 = wA - shiftf;
    const float disp1 = ((rq == 22u) ? wB : wA) - shiftf;

    // L stream for the pair: iL1 = iL + (rL0 >= 15); 3 loads cover both
    const unsigned pL  = (unsigned)q0 * 8u;
    const unsigned iL  = pL / 23u;
    const int      rL0 = (int)(pL - iL * 23u);
    const unsigned last = (unsigned)(NF - 1);
    const float A0 = __ldg(&fl[iL]);
    const float A1 = __ldg(&fl[min(iL + 1u, last)]);
    const float A2 = __ldg(&fl[min(iL + 2u, last)]);
    const bool  lc = (rL0 >= 15);
    const float A0b = lc ? A1 : A0;
    const float A1b = lc ? A2 : A1;
    const int   rL1 = lc ? (rL0 - 15) : (rL0 + 8);

    float2 res;
    res.x = cost_one(fr, A0,  A1,  rL0, w2,     base, disp0);
    res.y = cost_one(fr, A0b, A1b, rL1, w2 + 1, base, disp1);

    *reinterpret_cast<float2*>(out + q0) = res;
}

extern "C" void kernel_launch(void* const* d_in, const int* in_sizes, int n_in,
                              void* d_out, int out_size)
{
    const float* feat_l = (const float*)d_in[0];
    const float* feat_r = (const float*)d_in[1];
    const float* wflow  = (const float*)d_in[2];
    float* out = (float*)d_out;

    const int threads = 256;
    const int pairs   = TOTAL / 2;                       // 3,014,656
    const int blocks  = (pairs + threads - 1) / threads; // 11776
    costvol3d_kernel<<<blocks, threads>>>(feat_l, feat_r, wflow, out);
}

// round 7
// speedup vs baseline: 1.4611x; 1.0024x over previous
#include <cuda_runtime.h>

// CostVolume3D: B=8, H=128, W=256, C=8, MAX_DISP=12 -> D=23.
// tile(...,D) + raw reshape => every tiled read is orig.flat[p/23].
// Segment-sum over the <=4 constant-value runs of c=0..7.
// 4 outputs per thread (quad): shares row/x/shift; L-stream covered by 4
// loads + selects; second warp-tap division eliminated (p1-p0 in {0,8});
// segment logic done in float to balance alu->fma pipes.
// (Resubmission of the Round-5 candidate — prior bench hit an infra failure.)

#define B_ 8
#define H_ 128
#define W_ 256
#define C_ 8
#define D_ 23

static constexpr int TOTAL = B_ * H_ * W_ * D_;   // 6,029,312 (div by 4)
static constexpr int NF    = B_ * H_ * W_ * C_;   // 2,097,152
static constexpr int NW    = B_ * H_ * W_;        // 262,144

__global__ void __launch_bounds__(256)
costvol3d_kernel(const float* __restrict__ fl,
                 const float* __restrict__ fr,
                 const float* __restrict__ wf,
                 float* __restrict__ out)
{
    const int t  = blockIdx.x * blockDim.x + threadIdx.x;
    const int q0 = t * 4;
    if (q0 >= TOTAL) return;

    const unsigned LASTF = (unsigned)(NF - 1);
    const unsigned LASTW = (unsigned)(NW - 1);

    // Quad-invariant coordinates (quads never cross a row or batch slab).
    const int w2   = q0 & (W_ - 1);
    const int base = q0 - w2;
    const int x    = q0 >> 15;
    const int s    = x - 23 * ((x * 179) >> 12);   // x % 23 (x < 184)
    const float shiftf = (float)(s - 11);
    const float w2f    = (float)w2;

    // wflow: quotient crosses at most once inside a quad.
    const unsigned uq = (unsigned)q0;
    const unsigned wq = uq / 23u;
    const int      rq = (int)(uq - wq * 23u);
    const float wA = __ldg(wf + wq);
    const float wB = __ldg(wf + min(wq + 1u, LASTW));
    const float dispA = wA - shiftf;
    const float dispB = wB - shiftf;

    // L stream: quotients over the quad span iL..iL+2 (+1 for crossing).
    const unsigned pL  = uq * 8u;
    const unsigned iL  = pL / 23u;
    const int      rL0 = (int)(pL - iL * 23u);
    const float F0 = __ldg(fl + iL);
    const float F1 = __ldg(fl + min(iL + 1u, LASTF));
    const float F2 = __ldg(fl + min(iL + 2u, LASTF));
    const float F3 = __ldg(fl + min(iL + 3u, LASTF));

    float res[4];
#pragma unroll
    for (int k = 0; k < 4; k++) {
        const float disp = (rq + k < 23) ? dispA : dispB;

        // L-stream phase/values via compares (no per-k division)
        const int  off = rL0 + 8 * k;                 // <= 46
        const bool j1  = (off >= 23);
        const bool j2  = (off >= 46);
        const int  rL  = off - (j1 ? 23 : 0) - (j2 ? 23 : 0);
        const float A0 = j2 ? F2 : (j1 ? F1 : F0);
        const float A1 = j2 ? F3 : (j1 ? F2 : F1);

        // Bilinear coords — bit-identical to reference fp sequence
        const float xq   = (w2f + (float)k) - disp;
        const float x0f  = floorf(xq);
        const float frac = xq - x0f;
        int x0i = (int)x0f;
        x0i = min(max(x0i, 0), W_ - 1);

        // One division; second tap derived: p1 - p0 is 0 or 8.
        const unsigned p0 = (unsigned)(base + x0i) * 8u;
        const unsigned i0 = p0 / 23u;
        const int      r0 = (int)(p0 - i0 * 23u);
        const bool e   = (x0i < W_ - 1);
        const bool c15 = (r0 >= 15);
        const bool inc = e && c15;                    // i1 == i0 + 1 ?
        const int  r1  = e ? (r0 + 8 - (c15 ? 23 : 0)) : r0;

        // i1 in {i0, i0+1} -> 3 loads cover both warp taps.
        const float B0 = __ldg(fr + i0);
        const float B1 = __ldg(fr + min(i0 + 1u, LASTF));
        const float B2 = __ldg(fr + min(i0 + 2u, LASTF));
        const float C0 = inc ? B1 : B0;
        const float C1 = inc ? B2 : B1;

        // Segment sum in float (fma pipe): each stream flips once at t.
        const float tL = (float)min(23 - rL, 8);
        const float t0 = (float)min(23 - r0, 8);
        const float t1 = (float)min(23 - r1, 8);
        const float a  = fminf(tL, fminf(t0, t1));
        const float c3 = fmaxf(tL, fmaxf(t0, t1));
        const float b  = ((tL + t0) + t1) - (a + c3);

        const float L1  = (tL <= a) ? A1 : A0;
        const float v01 = (t0 <= a) ? B1 : B0;
        const float v11 = (t1 <= a) ? C1 : C0;
        const float L2  = (tL <= b) ? A1 : A0;
        const float v02 = (t0 <= b) ? B1 : B0;
        const float v12 = (t1 <= b) ? C1 : C0;

        const float g0 = fabsf(A0 - fmaf(frac, C0  - B0,  B0 ));
        const float g1 = fabsf(L1 - fmaf(frac, v11 - v01, v01));
        const float g2 = fabsf(L2 - fmaf(frac, v12 - v02, v02));
        const float g3 = fabsf(A1 - fmaf(frac, C1  - B1,  B1 ));

        float acc = a * g0;
        acc = fmaf(b  - a,  g1, acc);
        acc = fmaf(c3 - b,  g2, acc);
        acc = fmaf(8.0f - c3, g3, acc);
        res[k] = acc;
    }

    *reinterpret_cast<float4*>(out + q0) =
        make_float4(res[0], res[1], res[2], res[3]);
}

extern "C" void kernel_launch(void* const* d_in, const int* in_sizes, int n_in,
                              void* d_out, int out_size)
{
    const float* feat_l = (const float*)d_in[0];
    const float* feat_r = (const float*)d_in[1];
    const float* wflow  = (const float*)d_in[2];
    float* out = (float*)d_out;

    const int threads = 256;
    const int quads   = TOTAL / 4;                       // 1,507,328
    const int blocks  = (quads + threads - 1) / threads; // 5888
    costvol3d_kernel<<<blocks, threads>>>(feat_l, feat_r, wflow, out);
}